// round 5
// baseline (speedup 1.0000x reference)
#include <cuda_runtime.h>
#include <cfloat>
#include <cstdint>

// Problem constants
#define B_   65536
#define I_   640     // input dim (K of encode GEMM); 160 int32 groups
#define L_   2560    // latent dim
#define K_   32      // top-k
#define C_   64      // candidates per row (approx top-C, rescored exactly)

// Encode tiling
#define BM   64
#define BN   128
#define NTHR 256

// ---------------------------------------------------------------------------
// Device-global scratch (no allocation allowed)
// ---------------------------------------------------------------------------
__device__ float  g_WdT[(size_t)L_ * I_];    // transposed decoder
__device__ int8_t g_xq[(size_t)B_ * I_];     // x quantized int8
__device__ float  g_xs[B_];                  // per-row x scale
__device__ int8_t g_wq[(size_t)L_ * I_];     // We quantized int8
__device__ float  g_ws[L_];                  // per-row We scale
__device__ short  g_cand[(size_t)B_ * C_];   // candidate col indices

// ---------------------------------------------------------------------------
// SMEM layout for encode kernel (byte offsets)
// ---------------------------------------------------------------------------
#define SM_AS  0        // A int32 [64][160]               40960
#define SM_BS  40960    // B int32 [16][132] (padded)       8448
#define SM_CS  49408    // C float [64][129]               33024
#define SM_SV  82432    // topC vals [64][65] f            16640
#define SM_SI  99072    // topC idx  [64][65] s             8320
#define SM_SX  107392   // 64 x-scales                       256
#define SM_SW  107648   // 128 w-scales                      512
#define SM_BE  108160   // 128 bias                          512
#define SM_TOT 108672

// ---------------------------------------------------------------------------
// Kernel: transpose Wd [I_, L_] -> WdT [L_, I_]
// ---------------------------------------------------------------------------
__global__ void transpose_wd_kernel(const float* __restrict__ Wd) {
    __shared__ float tile[32][33];
    const int l0 = blockIdx.x * 32, i0 = blockIdx.y * 32;
    const int tx = threadIdx.x, ty = threadIdx.y;
    #pragma unroll
    for (int r = ty; r < 32; r += 8)
        tile[r][tx] = Wd[(size_t)(i0 + r) * L_ + l0 + tx];
    __syncthreads();
    #pragma unroll
    for (int r = ty; r < 32; r += 8)
        g_WdT[(size_t)(l0 + r) * I_ + i0 + tx] = tile[tx][r];
}

// ---------------------------------------------------------------------------
// Kernel: per-row int8 quantization of a [nrows, 640] fp32 matrix
//   one warp per row; 8 rows per block
// ---------------------------------------------------------------------------
__device__ __forceinline__ int q8(float v, float inv) {
    int a = __float2int_rn(v * inv);
    return max(-127, min(127, a));
}

__global__ void __launch_bounds__(256)
quant_rows_kernel(const float* __restrict__ src, int8_t* __restrict__ dst,
                  float* __restrict__ scales, int nrows) {
    const int row  = blockIdx.x * 8 + (threadIdx.x >> 5);
    const int lane = threadIdx.x & 31;
    if (row >= nrows) return;
    const float4* s = (const float4*)(src + (size_t)row * I_);
    float4 v[5];
    float m = 0.f;
    #pragma unroll
    for (int q = 0; q < 5; ++q) {
        v[q] = s[lane + q * 32];
        m = fmaxf(m, fmaxf(fmaxf(fabsf(v[q].x), fabsf(v[q].y)),
                           fmaxf(fabsf(v[q].z), fabsf(v[q].w))));
    }
    #pragma unroll
    for (int sh = 16; sh; sh >>= 1) m = fmaxf(m, __shfl_xor_sync(~0u, m, sh));
    m = fmaxf(m, 1e-30f);
    const float inv = 127.f / m;
    if (lane == 0) scales[row] = m / 127.f;
    int* d = (int*)(dst + (size_t)row * I_);
    #pragma unroll
    for (int q = 0; q < 5; ++q) {
        int a = q8(v[q].x, inv), b = q8(v[q].y, inv);
        int c = q8(v[q].z, inv), e = q8(v[q].w, inv);
        d[lane + q * 32] = (a & 0xFF) | ((b & 0xFF) << 8) |
                           ((c & 0xFF) << 16) | ((e & 0xFF) << 24);
    }
}

// ---------------------------------------------------------------------------
// Kernel: int8 DP4A encode GEMM + fused approx top-C + zero-fill
//   grid = B_/64 = 1024, 256 threads, 2 CTAs/SM
//   latent[b,l] ~= (int dot) * sx[b] * sw[l] + be[l]
// ---------------------------------------------------------------------------
__global__ void __launch_bounds__(NTHR, 2)
encode_topk_kernel(const float* __restrict__ be,
                   float* __restrict__ sparse_out) {
    extern __shared__ __align__(16) char smem[];
    int*   As  = (int*)(smem + SM_AS);    // [m][k4] m*160+k4
    int*   Bs  = (int*)(smem + SM_BS);    // [k4][n] k4*132+n
    float* Cs  = (float*)(smem + SM_CS);  // [m][n]  m*129+n
    float* sv  = (float*)(smem + SM_SV);  // [m][65]
    short* si  = (short*)(smem + SM_SI);  // [m][65]
    float* sxs = (float*)(smem + SM_SX);
    float* sws = (float*)(smem + SM_SW);
    float* sbe = (float*)(smem + SM_BE);

    const int tid  = threadIdx.x;
    const int tx   = tid & 15;   // 8 cols each
    const int ty   = tid >> 4;   // 4 rows each
    const int row0 = blockIdx.x * BM;

    // init candidate lists
    for (int i = tid; i < BM * C_; i += NTHR) {
        int r = i / C_, k = i % C_;
        sv[r * 65 + k] = -FLT_MAX;
        si[r * 65 + k] = 32767;
    }
    // stage full A (contiguous int32 copy: 64 rows x 160 int32)
    {
        const int* gx = (const int*)g_xq + (size_t)row0 * 160;
        #pragma unroll 8
        for (int u = tid; u < BM * 160; u += NTHR) As[u] = gx[u];
    }
    if (tid < BM) sxs[tid] = g_xs[row0 + tid];

    float minv = -FLT_MAX;
    int   mini = 32767;
    const int* gw = (const int*)g_wq;

    for (int ct = 0; ct < L_ / BN; ++ct) {
        const int col0 = ct * BN;
        if (tid < BN) { sws[tid] = g_ws[col0 + tid]; sbe[tid] = be[col0 + tid]; }

        int acc[4][8];
        #pragma unroll
        for (int i = 0; i < 4; ++i)
            #pragma unroll
            for (int j = 0; j < 8; ++j) acc[i][j] = 0;

        for (int k0 = 0; k0 < 160; k0 += 16) {
            // stage B: 128 cols x 16 int32
            #pragma unroll
            for (int it = 0; it < 8; ++it) {
                int u = tid + it * NTHR;
                int n = u >> 4, k4 = u & 15;
                Bs[k4 * 132 + n] = gw[(size_t)(col0 + n) * 160 + k0 + k4];
            }
            __syncthreads();

            #pragma unroll
            for (int k4 = 0; k4 < 16; ++k4) {
                int a0 = As[(ty * 4 + 0) * 160 + k0 + k4];
                int a1 = As[(ty * 4 + 1) * 160 + k0 + k4];
                int a2 = As[(ty * 4 + 2) * 160 + k0 + k4];
                int a3 = As[(ty * 4 + 3) * 160 + k0 + k4];
                int4 b0 = *(const int4*)&Bs[k4 * 132 + tx * 8];
                int4 b1 = *(const int4*)&Bs[k4 * 132 + tx * 8 + 4];
                int b[8] = {b0.x, b0.y, b0.z, b0.w, b1.x, b1.y, b1.z, b1.w};
                #pragma unroll
                for (int j = 0; j < 8; ++j) {
                    acc[0][j] = __dp4a(a0, b[j], acc[0][j]);
                    acc[1][j] = __dp4a(a1, b[j], acc[1][j]);
                    acc[2][j] = __dp4a(a2, b[j], acc[2][j]);
                    acc[3][j] = __dp4a(a3, b[j], acc[3][j]);
                }
            }
            __syncthreads();
        }

        // epilogue: scale + bias -> Cs
        #pragma unroll
        for (int i = 0; i < 4; ++i) {
            float sx = sxs[ty * 4 + i];
            #pragma unroll
            for (int j = 0; j < 8; ++j) {
                int n = tx * 8 + j;
                Cs[(ty * 4 + i) * 129 + n] =
                    (float)acc[i][j] * (sx * sws[n]) + sbe[n];
            }
        }
        __syncthreads();

        // streaming top-C update: thread t owns row t
        if (tid < BM) {
            const int lbase = tid * 65;
            #pragma unroll 1
            for (int n = 0; n < BN; ++n) {
                float v = Cs[tid * 129 + n];
                int col = col0 + n;
                if (v > minv || (v == minv && col < mini)) {
                    int p = C_ - 1;
                    while (p > 0) {
                        float pv = sv[lbase + p - 1];
                        int   pi = si[lbase + p - 1];
                        if (v > pv || (v == pv && col < pi)) {
                            sv[lbase + p] = pv; si[lbase + p] = (short)pi; --p;
                        } else break;
                    }
                    sv[lbase + p] = v; si[lbase + p] = (short)col;
                    minv = sv[lbase + C_ - 1];
                    mini = si[lbase + C_ - 1];
                }
            }
        }
        __syncthreads();
    }

    // publish candidate indices
    if (tid < BM) {
        #pragma unroll
        for (int k = 0; k < C_; ++k)
            g_cand[(size_t)(row0 + tid) * C_ + k] = si[tid * 65 + k];
    }

    // zero-fill this block's sparse region
    float4 z = make_float4(0.f, 0.f, 0.f, 0.f);
    float4* sp = (float4*)(sparse_out + (size_t)row0 * L_);
    for (int i = tid; i < BM * L_ / 4; i += NTHR) sp[i] = z;
}

// ---------------------------------------------------------------------------
// Kernel: exact fp32 rescore (STRICT sequential-k fma chain, one thread per
//         candidate — arithmetic order matches round-2's zero-flip evidence)
//         + exact rank select + sparse scatter + fused decode.
//   One block per row, 128 threads.
// ---------------------------------------------------------------------------
__global__ void __launch_bounds__(128)
rescore_decode_kernel(const float* __restrict__ x,
                      const float* __restrict__ We,
                      const float* __restrict__ be,
                      const float* __restrict__ bd,
                      float* __restrict__ sparse_out,
                      float* __restrict__ recon) {
    __shared__ float4 sx4[I_ / 4];
    __shared__ float  cv[C_];
    __shared__ int    ci[C_];
    __shared__ float  sv2[K_];
    __shared__ int    si2[K_];
    const int b = blockIdx.x, t = threadIdx.x;

    const float4* xr = (const float4*)(x + (size_t)b * I_);
    for (int i = t; i < I_ / 4; i += 128) sx4[i] = xr[i];
    if (t < C_) ci[t] = (int)g_cand[(size_t)b * C_ + t];
    __syncthreads();

    // exact fp32 dot, strict in-order k chain
    if (t < C_) {
        const int col = ci[t];
        const float4* w = (const float4*)(We + (size_t)col * I_);
        float acc = 0.f;
        #pragma unroll 4
        for (int q = 0; q < I_ / 4; ++q) {
            float4 a = sx4[q];
            float4 v = __ldg(&w[q]);
            acc = fmaf(a.x, v.x, acc);
            acc = fmaf(a.y, v.y, acc);
            acc = fmaf(a.z, v.z, acc);
            acc = fmaf(a.w, v.w, acc);
        }
        cv[t] = acc + __ldg(&be[col]);
    }
    __syncthreads();

    // exact rank (val desc, idx asc — jax tie rules); winners scatter
    if (t < C_) {
        const float v  = cv[t];
        const int   id = ci[t];
        int rank = 0;
        #pragma unroll
        for (int c = 0; c < C_; ++c) {
            if (c == t) continue;
            float vc = cv[c]; int ic = ci[c];
            rank += (vc > v) || (vc == v && ic < id);
        }
        if (rank < K_) {
            sparse_out[(size_t)b * L_ + id] = v;
            sv2[rank] = v;
            si2[rank] = id;
        }
    }
    __syncthreads();

    // fused decode: recon[b,i] = bd[i] + sum_k v_k * WdT[idx_k, i]
    float acc[5];
    #pragma unroll
    for (int j = 0; j < 5; ++j) acc[j] = __ldg(&bd[t + j * 128]);
    #pragma unroll 1
    for (int k = 0; k < K_; ++k) {
        float v = sv2[k];
        const float* cw = g_WdT + (size_t)si2[k] * I_;
        #pragma unroll
        for (int j = 0; j < 5; ++j)
            acc[j] = fmaf(v, __ldg(&cw[t + j * 128]), acc[j]);
    }
    #pragma unroll
    for (int j = 0; j < 5; ++j)
        recon[(size_t)b * I_ + t + j * 128] = acc[j];
}

// ---------------------------------------------------------------------------
// Launch
// ---------------------------------------------------------------------------
extern "C" void kernel_launch(void* const* d_in, const int* in_sizes, int n_in,
                              void* d_out, int out_size) {
    const float* x  = (const float*)d_in[0];   // [65536, 640]
    const float* We = (const float*)d_in[1];   // [2560, 640]
    const float* be = (const float*)d_in[2];   // [2560]
    const float* Wd = (const float*)d_in[3];   // [640, 2560]
    const float* bd = (const float*)d_in[4];   // [640]

    float* recon  = (float*)d_out;                    // [B_, I_]
    float* sparse = (float*)d_out + (size_t)B_ * I_;  // [B_, L_]

    int8_t* xq; float* xs; int8_t* wq; float* ws;
    cudaGetSymbolAddress((void**)&xq, g_xq);
    cudaGetSymbolAddress((void**)&xs, g_xs);
    cudaGetSymbolAddress((void**)&wq, g_wq);
    cudaGetSymbolAddress((void**)&ws, g_ws);

    cudaFuncSetAttribute(encode_topk_kernel,
                         cudaFuncAttributeMaxDynamicSharedMemorySize, SM_TOT);

    transpose_wd_kernel<<<dim3(L_ / 32, I_ / 32), dim3(32, 8)>>>(Wd);
    quant_rows_kernel<<<B_ / 8, 256>>>(x, xq, xs, B_);
    quant_rows_kernel<<<L_ / 8, 256>>>(We, wq, ws, L_);
    encode_topk_kernel<<<B_ / BM, NTHR, SM_TOT>>>(be, sparse);
    rescore_decode_kernel<<<B_, 128>>>(x, We, be, bd, sparse, recon);
}

// round 6
// speedup vs baseline: 1.6445x; 1.6445x over previous
#include <cuda_runtime.h>
#include <cfloat>
#include <cstdint>

// Problem constants
#define B_   65536
#define I_   640     // input dim (K of encode GEMM); 160 int32 groups
#define L_   2560    // latent dim
#define K_   32      // top-k
#define C_   64      // candidates per row (approx top-C, rescored exactly)

// Encode tiling
#define BM   64
#define BN   128
#define NTHR 256

// ---------------------------------------------------------------------------
// Device-global scratch (no allocation allowed)
// ---------------------------------------------------------------------------
__device__ float  g_WdT[(size_t)L_ * I_];    // transposed decoder
__device__ int8_t g_xq[(size_t)B_ * I_];     // x quantized int8
__device__ float  g_xs[B_];                  // per-row x scale
__device__ int8_t g_wq[(size_t)L_ * I_];     // We quantized int8
__device__ float  g_ws[L_];                  // per-row We scale
__device__ short  g_cand[(size_t)B_ * C_];   // candidate col indices

// ---------------------------------------------------------------------------
// SMEM layout for encode kernel (byte offsets)
//   As is K-MAJOR: [160 k4][64 m]  -> mainloop A load is LDS.128 broadcast,
//   zero bank conflicts (round-5's [m][k4] layout was a 16-way conflict).
// ---------------------------------------------------------------------------
#define SM_AS  0        // A int32 [160][64]               40960
#define SM_BS  40960    // B int32 [16][132] (padded)       8448
#define SM_CS  49408    // C float [64][129]               33024
#define SM_SV  82432    // topC vals [64][65] f            16640
#define SM_SI  99072    // topC idx  [64][65] s             8320
#define SM_SX  107392   // 64 x-scales                       256
#define SM_SW  107648   // 128 w-scales                      512
#define SM_BE  108160   // 128 bias                          512
#define SM_TOT 108672

// ---------------------------------------------------------------------------
// Kernel: transpose Wd [I_, L_] -> WdT [L_, I_]
// ---------------------------------------------------------------------------
__global__ void transpose_wd_kernel(const float* __restrict__ Wd) {
    __shared__ float tile[32][33];
    const int l0 = blockIdx.x * 32, i0 = blockIdx.y * 32;
    const int tx = threadIdx.x, ty = threadIdx.y;
    #pragma unroll
    for (int r = ty; r < 32; r += 8)
        tile[r][tx] = Wd[(size_t)(i0 + r) * L_ + l0 + tx];
    __syncthreads();
    #pragma unroll
    for (int r = ty; r < 32; r += 8)
        g_WdT[(size_t)(l0 + r) * I_ + i0 + tx] = tile[tx][r];
}

// ---------------------------------------------------------------------------
// Kernel: per-row int8 quantization of a [nrows, 640] fp32 matrix
// ---------------------------------------------------------------------------
__device__ __forceinline__ int q8(float v, float inv) {
    int a = __float2int_rn(v * inv);
    return max(-127, min(127, a));
}

__global__ void __launch_bounds__(256)
quant_rows_kernel(const float* __restrict__ src, int8_t* __restrict__ dst,
                  float* __restrict__ scales, int nrows) {
    const int row  = blockIdx.x * 8 + (threadIdx.x >> 5);
    const int lane = threadIdx.x & 31;
    if (row >= nrows) return;
    const float4* s = (const float4*)(src + (size_t)row * I_);
    float4 v[5];
    float m = 0.f;
    #pragma unroll
    for (int q = 0; q < 5; ++q) {
        v[q] = s[lane + q * 32];
        m = fmaxf(m, fmaxf(fmaxf(fabsf(v[q].x), fabsf(v[q].y)),
                           fmaxf(fabsf(v[q].z), fabsf(v[q].w))));
    }
    #pragma unroll
    for (int sh = 16; sh; sh >>= 1) m = fmaxf(m, __shfl_xor_sync(~0u, m, sh));
    m = fmaxf(m, 1e-30f);
    const float inv = 127.f / m;
    if (lane == 0) scales[row] = m / 127.f;
    int* d = (int*)(dst + (size_t)row * I_);
    #pragma unroll
    for (int q = 0; q < 5; ++q) {
        int a = q8(v[q].x, inv), b = q8(v[q].y, inv);
        int c = q8(v[q].z, inv), e = q8(v[q].w, inv);
        d[lane + q * 32] = (a & 0xFF) | ((b & 0xFF) << 8) |
                           ((c & 0xFF) << 16) | ((e & 0xFF) << 24);
    }
}

// ---------------------------------------------------------------------------
// Kernel: int8 DP4A encode GEMM + fused approx top-C + zero-fill
//   grid = B_/64 = 1024, 256 threads, 2 CTAs/SM
//   latent[b,l] ~= (int dot) * sx[b] * sw[l] + be[l]
// ---------------------------------------------------------------------------
__global__ void __launch_bounds__(NTHR, 2)
encode_topk_kernel(const float* __restrict__ be,
                   float* __restrict__ sparse_out) {
    extern __shared__ __align__(16) char smem[];
    int*   As  = (int*)(smem + SM_AS);    // [k4][m]  k4*64+m  (K-MAJOR)
    int*   Bs  = (int*)(smem + SM_BS);    // [k4][n]  k4*132+n
    float* Cs  = (float*)(smem + SM_CS);  // [m][n]   m*129+n
    float* sv  = (float*)(smem + SM_SV);  // [m][65]
    short* si  = (short*)(smem + SM_SI);  // [m][65]
    float* sxs = (float*)(smem + SM_SX);
    float* sws = (float*)(smem + SM_SW);
    float* sbe = (float*)(smem + SM_BE);

    const int tid  = threadIdx.x;
    const int tx   = tid & 15;   // 8 cols each
    const int ty   = tid >> 4;   // 4 rows each
    const int row0 = blockIdx.x * BM;

    // init candidate lists
    for (int i = tid; i < BM * C_; i += NTHR) {
        int r = i / C_, k = i % C_;
        sv[r * 65 + k] = -FLT_MAX;
        si[r * 65 + k] = 32767;
    }
    // stage full A transposed to [k4][m] (one-time; write conflicts amortized)
    {
        const int* gx = (const int*)g_xq + (size_t)row0 * 160;
        #pragma unroll 8
        for (int u = tid; u < BM * 160; u += NTHR) {
            int m = u / 160, k4 = u % 160;
            As[k4 * 64 + m] = gx[u];
        }
    }
    if (tid < BM) sxs[tid] = g_xs[row0 + tid];

    float minv = -FLT_MAX;
    int   mini = 32767;
    const int* gw = (const int*)g_wq;

    for (int ct = 0; ct < L_ / BN; ++ct) {
        const int col0 = ct * BN;
        if (tid < BN) { sws[tid] = g_ws[col0 + tid]; sbe[tid] = be[col0 + tid]; }

        int acc[4][8];
        #pragma unroll
        for (int i = 0; i < 4; ++i)
            #pragma unroll
            for (int j = 0; j < 8; ++j) acc[i][j] = 0;

        for (int k0 = 0; k0 < 160; k0 += 16) {
            // stage B: 128 cols x 16 int32
            #pragma unroll
            for (int it = 0; it < 8; ++it) {
                int u = tid + it * NTHR;
                int n = u >> 4, k4 = u & 15;
                Bs[k4 * 132 + n] = gw[(size_t)(col0 + n) * 160 + k0 + k4];
            }
            __syncthreads();

            #pragma unroll
            for (int k4 = 0; k4 < 16; ++k4) {
                int4 a4 = *(const int4*)&As[(k0 + k4) * 64 + ty * 4];
                int4 b0 = *(const int4*)&Bs[k4 * 132 + tx * 8];
                int4 b1 = *(const int4*)&Bs[k4 * 132 + tx * 8 + 4];
                int b[8] = {b0.x, b0.y, b0.z, b0.w, b1.x, b1.y, b1.z, b1.w};
                #pragma unroll
                for (int j = 0; j < 8; ++j) {
                    acc[0][j] = __dp4a(a4.x, b[j], acc[0][j]);
                    acc[1][j] = __dp4a(a4.y, b[j], acc[1][j]);
                    acc[2][j] = __dp4a(a4.z, b[j], acc[2][j]);
                    acc[3][j] = __dp4a(a4.w, b[j], acc[3][j]);
                }
            }
            __syncthreads();
        }

        // epilogue: scale + bias -> Cs
        #pragma unroll
        for (int i = 0; i < 4; ++i) {
            float sx = sxs[ty * 4 + i];
            #pragma unroll
            for (int j = 0; j < 8; ++j) {
                int n = tx * 8 + j;
                Cs[(ty * 4 + i) * 129 + n] =
                    (float)acc[i][j] * (sx * sws[n]) + sbe[n];
            }
        }
        __syncthreads();

        // streaming top-C update: thread t owns row t
        if (tid < BM) {
            const int lbase = tid * 65;
            #pragma unroll 1
            for (int n = 0; n < BN; ++n) {
                float v = Cs[tid * 129 + n];
                int col = col0 + n;
                if (v > minv || (v == minv && col < mini)) {
                    int p = C_ - 1;
                    while (p > 0) {
                        float pv = sv[lbase + p - 1];
                        int   pi = si[lbase + p - 1];
                        if (v > pv || (v == pv && col < pi)) {
                            sv[lbase + p] = pv; si[lbase + p] = (short)pi; --p;
                        } else break;
                    }
                    sv[lbase + p] = v; si[lbase + p] = (short)col;
                    minv = sv[lbase + C_ - 1];
                    mini = si[lbase + C_ - 1];
                }
            }
        }
        __syncthreads();
    }

    // publish candidate indices
    if (tid < BM) {
        #pragma unroll
        for (int k = 0; k < C_; ++k)
            g_cand[(size_t)(row0 + tid) * C_ + k] = si[tid * 65 + k];
    }

    // zero-fill this block's sparse region
    float4 z = make_float4(0.f, 0.f, 0.f, 0.f);
    float4* sp = (float4*)(sparse_out + (size_t)row0 * L_);
    for (int i = tid; i < BM * L_ / 4; i += NTHR) sp[i] = z;
}

// ---------------------------------------------------------------------------
// Kernel: exact fp32 rescore (STRICT sequential-k fma chain — zero-flip
//         arithmetic class) + exact rank select + scatter + fused decode.
//   One block per row, 128 threads.
// ---------------------------------------------------------------------------
__global__ void __launch_bounds__(128)
rescore_decode_kernel(const float* __restrict__ x,
                      const float* __restrict__ We,
                      const float* __restrict__ be,
                      const float* __restrict__ bd,
                      float* __restrict__ sparse_out,
                      float* __restrict__ recon) {
    __shared__ float4 sx4[I_ / 4];
    __shared__ float  cv[C_];
    __shared__ int    ci[C_];
    __shared__ float  sv2[K_];
    __shared__ int    si2[K_];
    const int b = blockIdx.x, t = threadIdx.x;

    const float4* xr = (const float4*)(x + (size_t)b * I_);
    for (int i = t; i < I_ / 4; i += 128) sx4[i] = xr[i];
    if (t < C_) ci[t] = (int)g_cand[(size_t)b * C_ + t];
    __syncthreads();

    // exact fp32 dot, strict in-order k chain
    if (t < C_) {
        const int col = ci[t];
        const float4* w = (const float4*)(We + (size_t)col * I_);
        float acc = 0.f;
        #pragma unroll 4
        for (int q = 0; q < I_ / 4; ++q) {
            float4 a = sx4[q];
            float4 v = __ldg(&w[q]);
            acc = fmaf(a.x, v.x, acc);
            acc = fmaf(a.y, v.y, acc);
            acc = fmaf(a.z, v.z, acc);
            acc = fmaf(a.w, v.w, acc);
        }
        cv[t] = acc + __ldg(&be[col]);
    }
    __syncthreads();

    // exact rank (val desc, idx asc — jax tie rules); winners scatter
    if (t < C_) {
        const float v  = cv[t];
        const int   id = ci[t];
        int rank = 0;
        #pragma unroll
        for (int c = 0; c < C_; ++c) {
            if (c == t) continue;
            float vc = cv[c]; int ic = ci[c];
            rank += (vc > v) || (vc == v && ic < id);
        }
        if (rank < K_) {
            sparse_out[(size_t)b * L_ + id] = v;
            sv2[rank] = v;
            si2[rank] = id;
        }
    }
    __syncthreads();

    // fused decode: recon[b,i] = bd[i] + sum_k v_k * WdT[idx_k, i]
    float acc[5];
    #pragma unroll
    for (int j = 0; j < 5; ++j) acc[j] = __ldg(&bd[t + j * 128]);
    #pragma unroll 1
    for (int k = 0; k < K_; ++k) {
        float v = sv2[k];
        const float* cw = g_WdT + (size_t)si2[k] * I_;
        #pragma unroll
        for (int j = 0; j < 5; ++j)
            acc[j] = fmaf(v, __ldg(&cw[t + j * 128]), acc[j]);
    }
    #pragma unroll
    for (int j = 0; j < 5; ++j)
        recon[(size_t)b * I_ + t + j * 128] = acc[j];
}

// ---------------------------------------------------------------------------
// Launch
// ---------------------------------------------------------------------------
extern "C" void kernel_launch(void* const* d_in, const int* in_sizes, int n_in,
                              void* d_out, int out_size) {
    const float* x  = (const float*)d_in[0];   // [65536, 640]
    const float* We = (const float*)d_in[1];   // [2560, 640]
    const float* be = (const float*)d_in[2];   // [2560]
    const float* Wd = (const float*)d_in[3];   // [640, 2560]
    const float* bd = (const float*)d_in[4];   // [640]

    float* recon  = (float*)d_out;                    // [B_, I_]
    float* sparse = (float*)d_out + (size_t)B_ * I_;  // [B_, L_]

    int8_t* xq; float* xs; int8_t* wq; float* ws;
    cudaGetSymbolAddress((void**)&xq, g_xq);
    cudaGetSymbolAddress((void**)&xs, g_xs);
    cudaGetSymbolAddress((void**)&wq, g_wq);
    cudaGetSymbolAddress((void**)&ws, g_ws);

    cudaFuncSetAttribute(encode_topk_kernel,
                         cudaFuncAttributeMaxDynamicSharedMemorySize, SM_TOT);

    transpose_wd_kernel<<<dim3(L_ / 32, I_ / 32), dim3(32, 8)>>>(Wd);
    quant_rows_kernel<<<B_ / 8, 256>>>(x, xq, xs, B_);
    quant_rows_kernel<<<L_ / 8, 256>>>(We, wq, ws, L_);
    encode_topk_kernel<<<B_ / BM, NTHR, SM_TOT>>>(be, sparse);
    rescore_decode_kernel<<<B_, 128>>>(x, We, be, bd, sparse, recon);
}

// round 7
// speedup vs baseline: 2.4778x; 1.5067x over previous
#include <cuda_runtime.h>
#include <cfloat>
#include <cstdint>

// Problem constants
#define B_   65536
#define I_   640     // input dim (K of encode GEMM)
#define L_   2560    // latent dim
#define K_   32      // top-k

// Encode tiling: block = 64 rows x 128 cols, 256 threads, 2 CTAs/SM
#define BM   64
#define BN   128
#define NTHR 256

typedef unsigned long long u64;

// ---------------------------------------------------------------------------
// Device-global scratch (no allocation allowed)
// ---------------------------------------------------------------------------
__device__ float g_WdT[(size_t)L_ * I_];   // Wd transposed  [2560][640]
__device__ float g_weT[(size_t)I_ * L_];   // We transposed  [640][2560]
__device__ float g_xT [(size_t)I_ * B_];   // x  transposed  [640][65536]
__device__ float g_topk_v[(size_t)B_ * K_];
__device__ int   g_topk_i[(size_t)B_ * K_];

// ---------------------------------------------------------------------------
// Packed f32x2 helpers (sm_100-family base ISA; SASS FFMA2)
// ---------------------------------------------------------------------------
__device__ __forceinline__ u64 pack2(float lo, float hi) {
    u64 d; asm("mov.b64 %0, {%1, %2};" : "=l"(d) : "f"(lo), "f"(hi)); return d;
}
__device__ __forceinline__ float2 unpack2(u64 v) {
    float2 r; asm("mov.b64 {%0, %1}, %2;" : "=f"(r.x), "=f"(r.y) : "l"(v));
    return r;
}
__device__ __forceinline__ void ffma2(u64& d, u64 a, u64 b) {
    asm("fma.rn.f32x2 %0, %1, %2, %0;" : "+l"(d) : "l"(a), "l"(b));
}

// ---------------------------------------------------------------------------
// SMEM layout for encode kernel (byte offsets)
//   As k-major [32][64] f32, Bs k-major [32][128] f32 — staging is straight
//   coalesced copy (conflict-free), mainloop loads broadcast/dedup.
// ---------------------------------------------------------------------------
#define SM_AS   0        //  8192
#define SM_BS   8192     // 16384
#define SM_CS   24576    // Cs [64][129] f32   33024
#define SM_SV   57600    // sv [64][33]  f32    8448
#define SM_SI   66048    // si [64][33]  i16    4224
#define SM_BE   70272    // sbe[128]     f32     512
#define SM_TOT  70784

// ---------------------------------------------------------------------------
// Kernel: generic 32x32 tiled transpose  dst[c][r] = src[r][c]
//   grid = (cols/32, rows/32), block = (32, 8)
// ---------------------------------------------------------------------------
__global__ void transpose_kernel(const float* __restrict__ src,
                                 float* __restrict__ dst,
                                 int rows, int cols) {
    __shared__ float t[32][33];
    const int c0 = blockIdx.x * 32, r0 = blockIdx.y * 32;
    const int tx = threadIdx.x, ty = threadIdx.y;
    #pragma unroll
    for (int r = ty; r < 32; r += 8)
        t[r][tx] = src[(size_t)(r0 + r) * cols + c0 + tx];
    __syncthreads();
    #pragma unroll
    for (int r = ty; r < 32; r += 8)
        dst[(size_t)(c0 + r) * rows + r0 + tx] = t[tx][r];
}

// ---------------------------------------------------------------------------
// Kernel: exact fp32 encode GEMM (FFMA2) + exact streaming top-32 + scatter
//   latents[b,l] = (sum_k x[b,k]*We[l,k], strict sequential k) + be[l]
//   Same per-value arithmetic as round-2's zero-flip fp32 kernel.
// ---------------------------------------------------------------------------
__global__ void __launch_bounds__(NTHR, 2)
encode_topk_kernel(const float* __restrict__ be,
                   float* __restrict__ sparse_out) {
    extern __shared__ __align__(16) char smem[];
    float* As  = (float*)(smem + SM_AS);   // [k][64]
    float* Bs  = (float*)(smem + SM_BS);   // [k][128]
    float* Cs  = (float*)(smem + SM_CS);   // [m][129]
    float* sv  = (float*)(smem + SM_SV);   // [m][33]
    short* si  = (short*)(smem + SM_SI);   // [m][33]
    float* sbe = (float*)(smem + SM_BE);

    const int tid  = threadIdx.x;
    const int tx   = tid & 15;   // 8 cols each
    const int ty   = tid >> 4;   // 4 rows each
    const int row0 = blockIdx.x * BM;

    // init top-k lists
    for (int i = tid; i < BM * K_; i += NTHR) {
        int r = i >> 5, k = i & 31;
        sv[r * 33 + k] = -FLT_MAX;
        si[r * 33 + k] = 32767;
    }

    float minv = -FLT_MAX;
    int   mini = 32767;

    for (int ct = 0; ct < L_ / BN; ++ct) {
        const int col0 = ct * BN;
        if (tid < BN) sbe[tid] = be[col0 + tid];

        u64 acc[4][4];
        #pragma unroll
        for (int i = 0; i < 4; ++i)
            #pragma unroll
            for (int j = 0; j < 4; ++j) acc[i][j] = 0ull;

        for (int k0 = 0; k0 < I_; k0 += 32) {
            __syncthreads();   // previous chunk consumed / sbe visible
            // stage A: As[k][m] = xT[k0+k][row0+m]   (512 float4, coalesced)
            #pragma unroll
            for (int it = 0; it < 2; ++it) {
                int u = tid + it * NTHR;
                int k = u >> 4, q = u & 15;
                ((float4*)As)[u] =
                    *(const float4*)(g_xT + (size_t)(k0 + k) * B_ + row0 + q * 4);
            }
            // stage B: Bs[k][n] = weT[k0+k][col0+n]   (1024 float4, coalesced)
            #pragma unroll
            for (int it = 0; it < 4; ++it) {
                int u = tid + it * NTHR;
                int k = u >> 5, q = u & 31;
                ((float4*)Bs)[u] =
                    *(const float4*)(g_weT + (size_t)(k0 + k) * L_ + col0 + q * 4);
            }
            __syncthreads();

            #pragma unroll 8
            for (int k = 0; k < 32; ++k) {
                float4 a4 = *(const float4*)&As[k * 64 + ty * 4];
                u64 aa0 = pack2(a4.x, a4.x);
                u64 aa1 = pack2(a4.y, a4.y);
                u64 aa2 = pack2(a4.z, a4.z);
                u64 aa3 = pack2(a4.w, a4.w);
                const float* bp = &Bs[k * 128 + tx * 8];
                u64 b0 = *(const u64*)(bp + 0);
                u64 b1 = *(const u64*)(bp + 2);
                u64 b2 = *(const u64*)(bp + 4);
                u64 b3 = *(const u64*)(bp + 6);
                ffma2(acc[0][0], aa0, b0); ffma2(acc[0][1], aa0, b1);
                ffma2(acc[0][2], aa0, b2); ffma2(acc[0][3], aa0, b3);
                ffma2(acc[1][0], aa1, b0); ffma2(acc[1][1], aa1, b1);
                ffma2(acc[1][2], aa1, b2); ffma2(acc[1][3], aa1, b3);
                ffma2(acc[2][0], aa2, b0); ffma2(acc[2][1], aa2, b1);
                ffma2(acc[2][2], aa2, b2); ffma2(acc[2][3], aa2, b3);
                ffma2(acc[3][0], aa3, b0); ffma2(acc[3][1], aa3, b1);
                ffma2(acc[3][2], aa3, b2); ffma2(acc[3][3], aa3, b3);
            }
        }

        // epilogue: unpack + bias -> Cs
        #pragma unroll
        for (int i = 0; i < 4; ++i) {
            #pragma unroll
            for (int j = 0; j < 4; ++j) {
                float2 p = unpack2(acc[i][j]);
                int n = tx * 8 + 2 * j;
                Cs[(ty * 4 + i) * 129 + n]     = p.x + sbe[n];
                Cs[(ty * 4 + i) * 129 + n + 1] = p.y + sbe[n + 1];
            }
        }
        __syncthreads();

        // exact streaming top-32: thread t owns row t (jax tie rules)
        if (tid < BM) {
            const int lbase = tid * 33;
            #pragma unroll 1
            for (int n = 0; n < BN; ++n) {
                float v = Cs[tid * 129 + n];
                int col = col0 + n;
                if (v > minv || (v == minv && col < mini)) {
                    int p = K_ - 1;
                    while (p > 0) {
                        float pv = sv[lbase + p - 1];
                        int   pi = si[lbase + p - 1];
                        if (v > pv || (v == pv && col < pi)) {
                            sv[lbase + p] = pv; si[lbase + p] = (short)pi; --p;
                        } else break;
                    }
                    sv[lbase + p] = v; si[lbase + p] = (short)col;
                    minv = sv[lbase + K_ - 1];
                    mini = si[lbase + K_ - 1];
                }
            }
        }
        __syncthreads();
    }

    // publish topk for decode
    if (tid < BM) {
        const size_t brow = (size_t)(row0 + tid);
        #pragma unroll
        for (int k = 0; k < K_; ++k) {
            g_topk_v[brow * K_ + k] = sv[tid * 33 + k];
            g_topk_i[brow * K_ + k] = (int)si[tid * 33 + k];
        }
    }

    // zero-fill this block's sparse region, then scatter winners
    {
        float4 z = make_float4(0.f, 0.f, 0.f, 0.f);
        float4* sp = (float4*)(sparse_out + (size_t)row0 * L_);
        for (int i = tid; i < BM * L_ / 4; i += NTHR) sp[i] = z;
    }
    __syncthreads();
    if (tid < BM) {
        const size_t brow = (size_t)(row0 + tid);
        #pragma unroll
        for (int k = 0; k < K_; ++k)
            sparse_out[brow * L_ + (int)si[tid * 33 + k]] = sv[tid * 33 + k];
    }
}

// ---------------------------------------------------------------------------
// Kernel: sparse decode.  recon[b,i] = bd[i] + sum_k v_k * WdT[idx_k, i]
// ---------------------------------------------------------------------------
__global__ void __launch_bounds__(128)
decode_kernel(const float* __restrict__ bd, float* __restrict__ recon) {
    __shared__ float sv[K_];
    __shared__ int   si[K_];
    const int b = blockIdx.x, t = threadIdx.x;
    if (t < K_) {
        sv[t] = g_topk_v[(size_t)b * K_ + t];
        si[t] = g_topk_i[(size_t)b * K_ + t];
    }
    __syncthreads();

    float acc[5];
    #pragma unroll
    for (int j = 0; j < 5; ++j) acc[j] = __ldg(&bd[t + j * 128]);
    #pragma unroll 1
    for (int k = 0; k < K_; ++k) {
        float v = sv[k];
        const float* cw = g_WdT + (size_t)si[k] * I_;
        #pragma unroll
        for (int j = 0; j < 5; ++j)
            acc[j] = fmaf(v, __ldg(&cw[t + j * 128]), acc[j]);
    }
    #pragma unroll
    for (int j = 0; j < 5; ++j)
        recon[(size_t)b * I_ + t + j * 128] = acc[j];
}

// ---------------------------------------------------------------------------
// Launch
// ---------------------------------------------------------------------------
extern "C" void kernel_launch(void* const* d_in, const int* in_sizes, int n_in,
                              void* d_out, int out_size) {
    const float* x  = (const float*)d_in[0];   // [65536, 640]
    const float* We = (const float*)d_in[1];   // [2560, 640]
    const float* be = (const float*)d_in[2];   // [2560]
    const float* Wd = (const float*)d_in[3];   // [640, 2560]
    const float* bd = (const float*)d_in[4];   // [640]

    float* recon  = (float*)d_out;                    // [B_, I_]
    float* sparse = (float*)d_out + (size_t)B_ * I_;  // [B_, L_]

    float *wdt, *wet, *xt;
    cudaGetSymbolAddress((void**)&wdt, g_WdT);
    cudaGetSymbolAddress((void**)&wet, g_weT);
    cudaGetSymbolAddress((void**)&xt,  g_xT);

    cudaFuncSetAttribute(encode_topk_kernel,
                         cudaFuncAttributeMaxDynamicSharedMemorySize, SM_TOT);

    // transposes: dst[c][r] = src[r][c]; grid = (cols/32, rows/32)
    transpose_kernel<<<dim3(L_ / 32, I_ / 32), dim3(32, 8)>>>(Wd, wdt, I_, L_);
    transpose_kernel<<<dim3(I_ / 32, L_ / 32), dim3(32, 8)>>>(We, wet, L_, I_);
    transpose_kernel<<<dim3(I_ / 32, B_ / 32), dim3(32, 8)>>>(x,  xt,  B_, I_);

    encode_topk_kernel<<<B_ / BM, NTHR, SM_TOT>>>(be, sparse);
    decode_kernel<<<B_, 128>>>(bd, recon);
}

// round 8
// speedup vs baseline: 4.4332x; 1.7892x over previous
#include <cuda_runtime.h>
#include <cfloat>
#include <cstdint>

// Problem constants
#define B_   65536
#define I_   640     // input dim (K of encode GEMM)
#define L_   2560    // latent dim
#define K_   32      // top-k

// Encode tiling: block tile 64 rows x 128 cols, 128 threads, 8x8 per thread
#define BM   64
#define BN   128
#define NTHR 128

typedef unsigned long long u64;

// ---------------------------------------------------------------------------
// Device-global scratch (no allocation allowed)
// ---------------------------------------------------------------------------
__device__ float g_WdT[(size_t)L_ * I_];   // Wd transposed  [2560][640]
__device__ float g_weT[(size_t)I_ * L_];   // We transposed  [640][2560]
__device__ float g_xT [(size_t)I_ * B_];   // x  transposed  [640][65536]
__device__ float g_topk_v[(size_t)B_ * K_];
__device__ int   g_topk_i[(size_t)B_ * K_];

// ---------------------------------------------------------------------------
// Packed f32x2 helpers (SASS FFMA2)
// ---------------------------------------------------------------------------
__device__ __forceinline__ u64 pack2(float lo, float hi) {
    u64 d; asm("mov.b64 %0, {%1, %2};" : "=l"(d) : "f"(lo), "f"(hi)); return d;
}
__device__ __forceinline__ float2 unpack2(u64 v) {
    float2 r; asm("mov.b64 {%0, %1}, %2;" : "=f"(r.x), "=f"(r.y) : "l"(v));
    return r;
}
__device__ __forceinline__ void ffma2(u64& d, u64 a, u64 b) {
    asm("fma.rn.f32x2 %0, %1, %2, %0;" : "+l"(d) : "l"(a), "l"(b));
}

// ---------------------------------------------------------------------------
// SMEM layout (byte offsets).  Cs overlays the dead As/Bs region between the
// end of a column-tile's k-loop and the next tile's staging.
// ---------------------------------------------------------------------------
#define SM_ASD  0        // u64 [32][64]  dup-packed A      16384
#define SM_BS   16384    // f32 [32][128]                   16384
#define SM_CS   0        // f32 [64][129] overlay           33024
#define SM_SV   33024    // f32 [64][33]                     8448
#define SM_SI   41472    // i16 [64][33]                     4224
#define SM_BE   45696    // f32 [128]                         512
#define SM_TOT  46208

// ---------------------------------------------------------------------------
// Kernel: generic 32x32 tiled transpose  dst[c][r] = src[r][c]
// ---------------------------------------------------------------------------
__global__ void transpose_kernel(const float* __restrict__ src,
                                 float* __restrict__ dst,
                                 int rows, int cols) {
    __shared__ float t[32][33];
    const int c0 = blockIdx.x * 32, r0 = blockIdx.y * 32;
    const int tx = threadIdx.x, ty = threadIdx.y;
    #pragma unroll
    for (int r = ty; r < 32; r += 8)
        t[r][tx] = src[(size_t)(r0 + r) * cols + c0 + tx];
    __syncthreads();
    #pragma unroll
    for (int r = ty; r < 32; r += 8)
        dst[(size_t)(c0 + r) * rows + r0 + tx] = t[tx][r];
}

// ---------------------------------------------------------------------------
// Fragment load/compute macros
//   A frag: 4 x LDS.128 of dup-packed u64 pairs (warp-broadcast addresses)
//   B frag: 2 x LDS.128, lanes cover 16 consecutive 16B lines (conflict-free)
// ---------------------------------------------------------------------------
#define LDA(kk, A)                                                      \
    {                                                                   \
        const ulonglong2* p =                                           \
            (const ulonglong2*)(Asd + (kk) * 64 + ty * 8);              \
        (A)[0] = p[0]; (A)[1] = p[1]; (A)[2] = p[2]; (A)[3] = p[3];     \
    }
#define LDB(kk, Bv)                                                     \
    {                                                                   \
        const float* q = Bs + (kk) * 128 + tx * 4;                      \
        (Bv)[0] = *(const ulonglong2*)(q);                              \
        (Bv)[1] = *(const ulonglong2*)(q + 64);                         \
    }
#define COMP(A, Bv)                                                     \
    {                                                                   \
        _Pragma("unroll")                                               \
        for (int i = 0; i < 4; ++i) {                                   \
            ffma2(acc[2*i][0],   (A)[i].x, (Bv)[0].x);                  \
            ffma2(acc[2*i][1],   (A)[i].x, (Bv)[0].y);                  \
            ffma2(acc[2*i][2],   (A)[i].x, (Bv)[1].x);                  \
            ffma2(acc[2*i][3],   (A)[i].x, (Bv)[1].y);                  \
            ffma2(acc[2*i+1][0], (A)[i].y, (Bv)[0].x);                  \
            ffma2(acc[2*i+1][1], (A)[i].y, (Bv)[0].y);                  \
            ffma2(acc[2*i+1][2], (A)[i].y, (Bv)[1].x);                  \
            ffma2(acc[2*i+1][3], (A)[i].y, (Bv)[1].y);                  \
        }                                                               \
    }

// ---------------------------------------------------------------------------
// Kernel: exact fp32 encode GEMM (FFMA2, 8x8 tile, prefetched) +
//         exact streaming top-32 + scatter.  grid = B_/64 = 1024.
// ---------------------------------------------------------------------------
__global__ void __launch_bounds__(NTHR, 4)
encode_topk_kernel(const float* __restrict__ be,
                   float* __restrict__ sparse_out) {
    extern __shared__ __align__(16) char smem[];
    u64*   Asd = (u64*)(smem + SM_ASD);    // [k][64] dup-packed
    float* Bs  = (float*)(smem + SM_BS);   // [k][128]
    float* Cs  = (float*)(smem + SM_CS);   // [64][129] overlay
    float* sv  = (float*)(smem + SM_SV);
    short* si  = (short*)(smem + SM_SI);
    float* sbe = (float*)(smem + SM_BE);

    const int tid  = threadIdx.x;
    const int tx   = tid & 15;   // col groups: tx*4 and 64+tx*4
    const int ty   = tid >> 4;   // row group: ty*8 .. ty*8+7
    const int row0 = blockIdx.x * BM;

    // init top-k lists
    for (int i = tid; i < BM * K_; i += NTHR) {
        int r = i >> 5, k = i & 31;
        sv[r * 33 + k] = -FLT_MAX;
        si[r * 33 + k] = 32767;
    }

    float minv = -FLT_MAX;
    int   mini = 32767;

    for (int ct = 0; ct < L_ / BN; ++ct) {
        const int col0 = ct * BN;

        u64 acc[8][4];
        #pragma unroll
        for (int i = 0; i < 8; ++i)
            #pragma unroll
            for (int j = 0; j < 4; ++j) acc[i][j] = 0ull;

        for (int k0 = 0; k0 < I_; k0 += 32) {
            __syncthreads();   // prior chunk / Cs-scan consumers done
            // stage A dup-packed: 512 float4 loads -> 2x uint4 stores each
            #pragma unroll
            for (int it = 0; it < 4; ++it) {
                int u = tid + it * NTHR;        // < 512
                int k = u >> 4, q = u & 15;
                float4 f = *(const float4*)(g_xT + (size_t)(k0 + k) * B_
                                            + row0 + q * 4);
                u64* d = Asd + k * 64 + q * 4;
                d[0] = pack2(f.x, f.x); d[1] = pack2(f.y, f.y);
                d[2] = pack2(f.z, f.z); d[3] = pack2(f.w, f.w);
            }
            // stage B: 1024 float4, coalesced, conflict-free
            #pragma unroll
            for (int it = 0; it < 8; ++it) {
                int u = tid + it * NTHR;        // < 1024
                int k = u >> 5, q = u & 31;
                ((float4*)Bs)[u] =
                    *(const float4*)(g_weT + (size_t)(k0 + k) * L_ + col0 + q * 4);
            }
            if (k0 == 0) sbe[tid] = be[col0 + tid];
            __syncthreads();

            // mainloop: register ping-pong prefetch, strict sequential k
            ulonglong2 aC[4], bC[2], aN[4], bN[2];
            LDA(0, aC); LDB(0, bC);
            #pragma unroll
            for (int k = 0; k < 32; k += 2) {
                LDA(k + 1, aN); LDB(k + 1, bN);
                COMP(aC, bC);
                if (k + 2 < 32) { LDA(k + 2, aC); LDB(k + 2, bC); }
                COMP(aN, bN);
            }
        }
        __syncthreads();   // all frag reads done before Cs overlays As/Bs

        // epilogue: unpack + bias -> Cs (overlay)
        #pragma unroll
        for (int i = 0; i < 8; ++i) {
            const int row = ty * 8 + i;
            #pragma unroll
            for (int j = 0; j < 4; ++j) {
                float2 p = unpack2(acc[i][j]);
                int n = (j < 2 ? tx * 4 + 2 * j : 64 + tx * 4 + 2 * (j - 2));
                Cs[row * 129 + n]     = p.x + sbe[n];
                Cs[row * 129 + n + 1] = p.y + sbe[n + 1];
            }
        }
        __syncthreads();

        // exact streaming top-32: thread t owns row t (jax tie rules)
        if (tid < BM) {
            const int lbase = tid * 33;
            #pragma unroll 1
            for (int n = 0; n < BN; ++n) {
                float v = Cs[tid * 129 + n];
                int col = col0 + n;
                if (v > minv || (v == minv && col < mini)) {
                    int p = K_ - 1;
                    while (p > 0) {
                        float pv = sv[lbase + p - 1];
                        int   pi = si[lbase + p - 1];
                        if (v > pv || (v == pv && col < pi)) {
                            sv[lbase + p] = pv; si[lbase + p] = (short)pi; --p;
                        } else break;
                    }
                    sv[lbase + p] = v; si[lbase + p] = (short)col;
                    minv = sv[lbase + K_ - 1];
                    mini = si[lbase + K_ - 1];
                }
            }
        }
        // next iteration's leading __syncthreads orders scan vs restaging
    }
    __syncthreads();

    // publish topk for decode
    if (tid < BM) {
        const size_t brow = (size_t)(row0 + tid);
        #pragma unroll
        for (int k = 0; k < K_; ++k) {
            g_topk_v[brow * K_ + k] = sv[tid * 33 + k];
            g_topk_i[brow * K_ + k] = (int)si[tid * 33 + k];
        }
    }

    // zero-fill this block's sparse region, then scatter winners
    {
        float4 z = make_float4(0.f, 0.f, 0.f, 0.f);
        float4* sp = (float4*)(sparse_out + (size_t)row0 * L_);
        for (int i = tid; i < BM * L_ / 4; i += NTHR) sp[i] = z;
    }
    __syncthreads();
    if (tid < BM) {
        const size_t brow = (size_t)(row0 + tid);
        #pragma unroll
        for (int k = 0; k < K_; ++k)
            sparse_out[brow * L_ + (int)si[tid * 33 + k]] = sv[tid * 33 + k];
    }
}

// ---------------------------------------------------------------------------
// Kernel: sparse decode.  recon[b,i] = bd[i] + sum_k v_k * WdT[idx_k, i]
// ---------------------------------------------------------------------------
__global__ void __launch_bounds__(128)
decode_kernel(const float* __restrict__ bd, float* __restrict__ recon) {
    __shared__ float sv[K_];
    __shared__ int   si[K_];
    const int b = blockIdx.x, t = threadIdx.x;
    if (t < K_) {
        sv[t] = g_topk_v[(size_t)b * K_ + t];
        si[t] = g_topk_i[(size_t)b * K_ + t];
    }
    __syncthreads();

    float acc[5];
    #pragma unroll
    for (int j = 0; j < 5; ++j) acc[j] = __ldg(&bd[t + j * 128]);
    #pragma unroll 1
    for (int k = 0; k < K_; ++k) {
        float v = sv[k];
        const float* cw = g_WdT + (size_t)si[k] * I_;
        #pragma unroll
        for (int j = 0; j < 5; ++j)
            acc[j] = fmaf(v, __ldg(&cw[t + j * 128]), acc[j]);
    }
    #pragma unroll
    for (int j = 0; j < 5; ++j)
        recon[(size_t)b * I_ + t + j * 128] = acc[j];
}

// ---------------------------------------------------------------------------
// Launch
// ---------------------------------------------------------------------------
extern "C" void kernel_launch(void* const* d_in, const int* in_sizes, int n_in,
                              void* d_out, int out_size) {
    const float* x  = (const float*)d_in[0];   // [65536, 640]
    const float* We = (const float*)d_in[1];   // [2560, 640]
    const float* be = (const float*)d_in[2];   // [2560]
    const float* Wd = (const float*)d_in[3];   // [640, 2560]
    const float* bd = (const float*)d_in[4];   // [640]

    float* recon  = (float*)d_out;                    // [B_, I_]
    float* sparse = (float*)d_out + (size_t)B_ * I_;  // [B_, L_]

    float *wdt, *wet, *xt;
    cudaGetSymbolAddress((void**)&wdt, g_WdT);
    cudaGetSymbolAddress((void**)&wet, g_weT);
    cudaGetSymbolAddress((void**)&xt,  g_xT);

    cudaFuncSetAttribute(encode_topk_kernel,
                         cudaFuncAttributeMaxDynamicSharedMemorySize, SM_TOT);

    transpose_kernel<<<dim3(L_ / 32, I_ / 32), dim3(32, 8)>>>(Wd, wdt, I_, L_);
    transpose_kernel<<<dim3(I_ / 32, L_ / 32), dim3(32, 8)>>>(We, wet, L_, I_);
    transpose_kernel<<<dim3(I_ / 32, B_ / 32), dim3(32, 8)>>>(x,  xt,  B_, I_);

    encode_topk_kernel<<<B_ / BM, NTHR, SM_TOT>>>(be, sparse);
    decode_kernel<<<B_, 128>>>(bd, recon);
}

// round 9
// speedup vs baseline: 4.6914x; 1.0582x over previous
#include <cuda_runtime.h>
#include <cfloat>
#include <cstdint>

// Problem constants
#define B_   65536
#define I_   640     // input dim (K of encode GEMM)
#define L_   2560    // latent dim
#define K_   32      // top-k

// Encode tiling: block tile 64 rows x 128 cols, 128 threads, 8x8 per thread
#define BM   64
#define BN   128
#define NTHR 128
#define CH   16                 // k per pipeline chunk
#define NC   (I_ / CH)          // 40 chunks

typedef unsigned long long u64;

// ---------------------------------------------------------------------------
// Device-global scratch (no allocation allowed)
// ---------------------------------------------------------------------------
__device__ float g_WdT[(size_t)L_ * I_];   // Wd transposed  [2560][640]
__device__ float g_weT[(size_t)I_ * L_];   // We transposed  [640][2560]
__device__ u64   g_xTd[(size_t)I_ * B_];   // x transposed + dup-packed (a,a)
__device__ float g_topk_v[(size_t)B_ * K_];
__device__ int   g_topk_i[(size_t)B_ * K_];

// ---------------------------------------------------------------------------
// Packed f32x2 helpers (SASS FFMA2)
// ---------------------------------------------------------------------------
__device__ __forceinline__ u64 pack2(float lo, float hi) {
    u64 d; asm("mov.b64 %0, {%1, %2};" : "=l"(d) : "f"(lo), "f"(hi)); return d;
}
__device__ __forceinline__ float2 unpack2(u64 v) {
    float2 r; asm("mov.b64 {%0, %1}, %2;" : "=f"(r.x), "=f"(r.y) : "l"(v));
    return r;
}
__device__ __forceinline__ void ffma2(u64& d, u64 a, u64 b) {
    asm("fma.rn.f32x2 %0, %1, %2, %0;" : "+l"(d) : "l"(a), "l"(b));
}
__device__ __forceinline__ uint32_t smem_u32(const void* p) {
    uint32_t a;
    asm("{ .reg .u64 t; cvta.to.shared.u64 t, %1; cvt.u32.u64 %0, t; }"
        : "=r"(a) : "l"(p));
    return a;
}
#define CP16(dst_u32, src_ptr) \
    asm volatile("cp.async.cg.shared.global [%0], [%1], 16;" \
                 :: "r"(dst_u32), "l"(src_ptr) : "memory")
#define CP_COMMIT()  asm volatile("cp.async.commit_group;" ::: "memory")
#define CP_WAIT0()   asm volatile("cp.async.wait_group 0;" ::: "memory")

// ---------------------------------------------------------------------------
// SMEM layout (byte offsets). Stage s at s*16384: A(8K dup u64) + B(8K f32).
// Cs overlays stage 0 as swizzled [64 rows][16 uint4] (one 64-col half-tile).
// ---------------------------------------------------------------------------
#define SM_STAGE(s) ((s) * 16384)
#define SM_A_OFF    0
#define SM_B_OFF    8192
#define SM_CS       0
#define SM_SV       32768   // f32 [64][33]  8448
#define SM_SI       41216   // i16 [64][33]  4224
#define SM_BE       45440   // f32 [128]      512
#define SM_TOT      45952

// ---------------------------------------------------------------------------
// Kernel: generic 32x32 tiled transpose  dst[c][r] = src[r][c]
// ---------------------------------------------------------------------------
__global__ void transpose_kernel(const float* __restrict__ src,
                                 float* __restrict__ dst,
                                 int rows, int cols) {
    __shared__ float t[32][33];
    const int c0 = blockIdx.x * 32, r0 = blockIdx.y * 32;
    const int tx = threadIdx.x, ty = threadIdx.y;
    #pragma unroll
    for (int r = ty; r < 32; r += 8)
        t[r][tx] = src[(size_t)(r0 + r) * cols + c0 + tx];
    __syncthreads();
    #pragma unroll
    for (int r = ty; r < 32; r += 8)
        dst[(size_t)(c0 + r) * rows + r0 + tx] = t[tx][r];
}

// ---------------------------------------------------------------------------
// Kernel: transpose + dup-pack x:  g_xTd[k][b] = (x[b][k], x[b][k])
// ---------------------------------------------------------------------------
__global__ void transpose_dup_kernel(const float* __restrict__ x) {
    __shared__ float t[32][33];
    const int k0 = blockIdx.x * 32, b0 = blockIdx.y * 32;
    const int tx = threadIdx.x, ty = threadIdx.y;
    #pragma unroll
    for (int r = ty; r < 32; r += 8)
        t[r][tx] = x[(size_t)(b0 + r) * I_ + k0 + tx];
    __syncthreads();
    #pragma unroll
    for (int r = ty; r < 32; r += 8) {
        float v = t[tx][r];
        g_xTd[(size_t)(k0 + r) * B_ + b0 + tx] = pack2(v, v);
    }
}

// ---------------------------------------------------------------------------
// Fragment load/compute macros (stage-relative)
// ---------------------------------------------------------------------------
#define LDA(base, kk, A)                                                \
    {                                                                   \
        const ulonglong2* p =                                           \
            (const ulonglong2*)((base) + (kk) * 512 + ty * 64);         \
        (A)[0] = p[0]; (A)[1] = p[1]; (A)[2] = p[2]; (A)[3] = p[3];     \
    }
#define LDB(base, kk, Bv)                                               \
    {                                                                   \
        const char* q = (base) + SM_B_OFF + (kk) * 512 + tx * 16;       \
        (Bv)[0] = *(const ulonglong2*)(q);                              \
        (Bv)[1] = *(const ulonglong2*)(q + 256);                        \
    }
#define COMP(A, Bv)                                                     \
    {                                                                   \
        _Pragma("unroll")                                               \
        for (int i = 0; i < 4; ++i) {                                   \
            ffma2(acc[2*i][0],   (A)[i].x, (Bv)[0].x);                  \
            ffma2(acc[2*i][1],   (A)[i].x, (Bv)[0].y);                  \
            ffma2(acc[2*i][2],   (A)[i].x, (Bv)[1].x);                  \
            ffma2(acc[2*i][3],   (A)[i].x, (Bv)[1].y);                  \
            ffma2(acc[2*i+1][0], (A)[i].y, (Bv)[0].x);                  \
            ffma2(acc[2*i+1][1], (A)[i].y, (Bv)[0].y);                  \
            ffma2(acc[2*i+1][2], (A)[i].y, (Bv)[1].x);                  \
            ffma2(acc[2*i+1][3], (A)[i].y, (Bv)[1].y);                  \
        }                                                               \
    }

// ---------------------------------------------------------------------------
// Kernel: exact fp32 encode GEMM (FFMA2, cp.async 2-stage) +
//         exact streaming top-32 (float4 swizzled scan) + scatter.
// ---------------------------------------------------------------------------
__global__ void __launch_bounds__(NTHR, 4)
encode_topk_kernel(const float* __restrict__ be,
                   float* __restrict__ sparse_out) {
    extern __shared__ __align__(16) char smem[];
    const uint32_t sb = smem_u32(smem);
    uint4* CsU = (uint4*)(smem + SM_CS);   // swizzled [64][16]
    float* sv  = (float*)(smem + SM_SV);
    short* si  = (short*)(smem + SM_SI);
    float* sbe = (float*)(smem + SM_BE);

    const int tid  = threadIdx.x;
    const int tx   = tid & 15;
    const int ty   = tid >> 4;
    const int row0 = blockIdx.x * BM;

    // init top-k lists
    for (int i = tid; i < BM * K_; i += NTHR) {
        int r = i >> 5, k = i & 31;
        sv[r * 33 + k] = -FLT_MAX;
        si[r * 33 + k] = 32767;
    }
    __syncthreads();

    // staging issue: chunk c -> stage s (512 x 16B for A, 512 x 16B for B)
    auto issue_chunk = [&](int ct, int c, int s) {
        const int k0   = c * CH;
        const int col0 = ct * BN;
        const uint32_t abase = sb + SM_STAGE(s) + SM_A_OFF;
        const uint32_t bbase = sb + SM_STAGE(s) + SM_B_OFF;
        #pragma unroll
        for (int it = 0; it < 4; ++it) {
            int u = tid + it * NTHR;      // 0..511
            int k = u >> 5, q = u & 31;
            const char* asrc = (const char*)(g_xTd
                + (size_t)(k0 + k) * B_ + row0 + q * 2);
            CP16(abase + k * 512 + q * 16, asrc);
            const char* bsrc = (const char*)(g_weT
                + (size_t)(k0 + k) * L_ + (col0 + q * 4));
            CP16(bbase + k * 512 + q * 16, bsrc);
        }
        CP_COMMIT();
    };

    float minv = -FLT_MAX;
    int   mini = 32767;

    // prefetch tile 0 chunk 0
    issue_chunk(0, 0, 0);
    if (tid < BN) sbe[tid] = be[tid];

    for (int ct = 0; ct < L_ / BN; ++ct) {
        const int col0 = ct * BN;

        u64 acc[8][4];
        #pragma unroll
        for (int i = 0; i < 8; ++i)
            #pragma unroll
            for (int j = 0; j < 4; ++j) acc[i][j] = 0ull;

        for (int c = 0; c < NC; ++c) {
            CP_WAIT0();
            __syncthreads();            // chunk c visible; c-1 consumers done
            if (c + 1 < NC) issue_chunk(ct, c + 1, (c + 1) & 1);

            const char* base = smem + SM_STAGE(c & 1);
            ulonglong2 aC[4], bC[2], aN[4], bN[2];
            LDA(base, 0, aC); LDB(base, 0, bC);
            #pragma unroll
            for (int k = 0; k < CH; k += 2) {
                LDA(base, k + 1, aN); LDB(base, k + 1, bN);
                COMP(aC, bC);
                if (k + 2 < CH) { LDA(base, k + 2, aC); LDB(base, k + 2, bC); }
                COMP(aN, bN);
            }
            __syncthreads();            // chunk c consumed before overwrite
        }

        // two 64-col halves: epilogue (swizzled Cs over stage 0) + scan
        #pragma unroll
        for (int h = 0; h < 2; ++h) {
            // epilogue: bias + swizzled store, one float4 per row
            #pragma unroll
            for (int i = 0; i < 8; ++i) {
                const int r = ty * 8 + i;
                float2 p0 = unpack2(acc[i][2 * h]);
                float2 p1 = unpack2(acc[i][2 * h + 1]);
                const int n0 = h * 64 + tx * 4;
                float4 f = make_float4(p0.x + sbe[n0],     p0.y + sbe[n0 + 1],
                                       p1.x + sbe[n0 + 2], p1.y + sbe[n0 + 3]);
                CsU[r * 16 + ((tx + r) & 15)] = *(uint4*)&f;
            }
            __syncthreads();

            // scan: thread t owns row t, 16 swizzled float4 reads
            if (tid < BM) {
                const int lbase = tid * 33;
                #pragma unroll 1
                for (int c4 = 0; c4 < 16; ++c4) {
                    uint4 u = CsU[tid * 16 + ((c4 + tid) & 15)];
                    float4 v = *(float4*)&u;
                    float vmax = fmaxf(fmaxf(v.x, v.y), fmaxf(v.z, v.w));
                    if (vmax < minv) continue;   // exact: ties have v==minv
                    const float vs[4] = {v.x, v.y, v.z, v.w};
                    #pragma unroll 1
                    for (int e = 0; e < 4; ++e) {
                        float val = vs[e];
                        int col = col0 + h * 64 + c4 * 4 + e;
                        if (val > minv || (val == minv && col < mini)) {
                            int p = K_ - 1;
                            while (p > 0) {
                                float pv = sv[lbase + p - 1];
                                int   pi = si[lbase + p - 1];
                                if (val > pv || (val == pv && col < pi)) {
                                    sv[lbase + p] = pv;
                                    si[lbase + p] = (short)pi; --p;
                                } else break;
                            }
                            sv[lbase + p] = val; si[lbase + p] = (short)col;
                            minv = sv[lbase + K_ - 1];
                            mini = si[lbase + K_ - 1];
                        }
                    }
                }
            }
            __syncthreads();
        }

        // prefetch next tile's chunk 0 (stage 0 free again) + next bias
        if (ct + 1 < L_ / BN) {
            issue_chunk(ct + 1, 0, 0);
            if (tid < BN) sbe[tid] = be[col0 + BN + tid];
        }
    }

    // publish topk for decode
    if (tid < BM) {
        const size_t brow = (size_t)(row0 + tid);
        #pragma unroll
        for (int k = 0; k < K_; ++k) {
            g_topk_v[brow * K_ + k] = sv[tid * 33 + k];
            g_topk_i[brow * K_ + k] = (int)si[tid * 33 + k];
        }
    }

    // zero-fill this block's sparse region, then scatter winners
    {
        float4 z = make_float4(0.f, 0.f, 0.f, 0.f);
        float4* sp = (float4*)(sparse_out + (size_t)row0 * L_);
        for (int i = tid; i < BM * L_ / 4; i += NTHR) sp[i] = z;
    }
    __syncthreads();
    if (tid < BM) {
        const size_t brow = (size_t)(row0 + tid);
        #pragma unroll
        for (int k = 0; k < K_; ++k)
            sparse_out[brow * L_ + (int)si[tid * 33 + k]] = sv[tid * 33 + k];
    }
}

// ---------------------------------------------------------------------------
// Kernel: sparse decode.  recon[b,i] = bd[i] + sum_k v_k * WdT[idx_k, i]
// ---------------------------------------------------------------------------
__global__ void __launch_bounds__(128)
decode_kernel(const float* __restrict__ bd, float* __restrict__ recon) {
    __shared__ float sv[K_];
    __shared__ int   si[K_];
    const int b = blockIdx.x, t = threadIdx.x;
    if (t < K_) {
        sv[t] = g_topk_v[(size_t)b * K_ + t];
        si[t] = g_topk_i[(size_t)b * K_ + t];
    }
    __syncthreads();

    float acc[5];
    #pragma unroll
    for (int j = 0; j < 5; ++j) acc[j] = __ldg(&bd[t + j * 128]);
    #pragma unroll 1
    for (int k = 0; k < K_; ++k) {
        float v = sv[k];
        const float* cw = g_WdT + (size_t)si[k] * I_;
        #pragma unroll
        for (int j = 0; j < 5; ++j)
            acc[j] = fmaf(v, __ldg(&cw[t + j * 128]), acc[j]);
    }
    #pragma unroll
    for (int j = 0; j < 5; ++j)
        recon[(size_t)b * I_ + t + j * 128] = acc[j];
}

// ---------------------------------------------------------------------------
// Launch
// ---------------------------------------------------------------------------
extern "C" void kernel_launch(void* const* d_in, const int* in_sizes, int n_in,
                              void* d_out, int out_size) {
    const float* x  = (const float*)d_in[0];   // [65536, 640]
    const float* We = (const float*)d_in[1];   // [2560, 640]
    const float* be = (const float*)d_in[2];   // [2560]
    const float* Wd = (const float*)d_in[3];   // [640, 2560]
    const float* bd = (const float*)d_in[4];   // [640]

    float* recon  = (float*)d_out;                    // [B_, I_]
    float* sparse = (float*)d_out + (size_t)B_ * I_;  // [B_, L_]

    float *wdt, *wet;
    cudaGetSymbolAddress((void**)&wdt, g_WdT);
    cudaGetSymbolAddress((void**)&wet, g_weT);

    cudaFuncSetAttribute(encode_topk_kernel,
                         cudaFuncAttributeMaxDynamicSharedMemorySize, SM_TOT);

    transpose_kernel<<<dim3(L_ / 32, I_ / 32), dim3(32, 8)>>>(Wd, wdt, I_, L_);
    transpose_kernel<<<dim3(I_ / 32, L_ / 32), dim3(32, 8)>>>(We, wet, L_, I_);
    transpose_dup_kernel<<<dim3(I_ / 32, B_ / 32), dim3(32, 8)>>>(x);

    encode_topk_kernel<<<B_ / BM, NTHR, SM_TOT>>>(be, sparse);
    decode_kernel<<<B_, 128>>>(bd, recon);
}